// round 5
// baseline (speedup 1.0000x reference)
#include <cuda_runtime.h>

#define M_TOT 16384
#define D_DIM 1024
#define N_DIM 64
#define L_SEQ 4096
#define B_SZ  4
#define CH    128
#define HALO  64

// scratch (static device globals — no allocation)
__device__ float g_u[M_TOT * N_DIM];   // 4 MB
__device__ float g_y[M_TOT * N_DIM];   // 4 MB

// C[M x P] = A[M x K] * B[P x K]^T, all row-major, dims divide tiles exactly.
// 256 threads as 16x16 (tx, ty); micro-tile TM x 4.
template <int BM, int BP, int BK, int TM>
__global__ void __launch_bounds__(256)
gemm_abt(const float* __restrict__ A, const float* __restrict__ Bm,
         float* __restrict__ C, int K, int P) {
    __shared__ float As[BM][BK + 1];
    __shared__ float Bs[BP][BK + 1];

    const int bm = blockIdx.x * BM;
    const int bp = blockIdx.y * BP;
    const int tid = threadIdx.x;
    const int tx = tid & 15;
    const int ty = tid >> 4;

    float acc[TM][4];
#pragma unroll
    for (int i = 0; i < TM; i++)
#pragma unroll
        for (int j = 0; j < 4; j++) acc[i][j] = 0.f;

    for (int k0 = 0; k0 < K; k0 += BK) {
        // load A tile (float4 over contiguous k)
#pragma unroll
        for (int i = tid; i < BM * (BK / 4); i += 256) {
            int r = i / (BK / 4), c = i % (BK / 4);
            float4 v = *(const float4*)(A + (size_t)(bm + r) * K + k0 + c * 4);
            As[r][c * 4 + 0] = v.x; As[r][c * 4 + 1] = v.y;
            As[r][c * 4 + 2] = v.z; As[r][c * 4 + 3] = v.w;
        }
        // load B tile
#pragma unroll
        for (int i = tid; i < BP * (BK / 4); i += 256) {
            int r = i / (BK / 4), c = i % (BK / 4);
            float4 v = *(const float4*)(Bm + (size_t)(bp + r) * K + k0 + c * 4);
            Bs[r][c * 4 + 0] = v.x; Bs[r][c * 4 + 1] = v.y;
            Bs[r][c * 4 + 2] = v.z; Bs[r][c * 4 + 3] = v.w;
        }
        __syncthreads();

#pragma unroll
        for (int kk = 0; kk < BK; kk++) {
            float a[TM], b[4];
#pragma unroll
            for (int i = 0; i < TM; i++) a[i] = As[ty * TM + i][kk];
#pragma unroll
            for (int j = 0; j < 4; j++) b[j] = Bs[tx * 4 + j][kk];
#pragma unroll
            for (int i = 0; i < TM; i++)
#pragma unroll
                for (int j = 0; j < 4; j++) acc[i][j] += a[i] * b[j];
        }
        __syncthreads();
    }

#pragma unroll
    for (int i = 0; i < TM; i++) {
        float4 v = make_float4(acc[i][0], acc[i][1], acc[i][2], acc[i][3]);
        *(float4*)(C + (size_t)(bm + ty * TM + i) * P + bp + tx * 4) = v;
    }
}

// Chunked-parallel diagonal SSM scan with decay halo.
// grid: (L/CH, B), block: N_DIM threads (one state dim each).
__global__ void __launch_bounds__(N_DIM)
ssm_scan(const float* __restrict__ u, float* __restrict__ y,
         const float* __restrict__ logA, const float* __restrict__ Bp,
         const float* __restrict__ Cp, const float* __restrict__ logdt) {
    const int n = threadIdx.x;
    const int b = blockIdx.y;
    const int t0 = blockIdx.x * CH;

    const float dt = expf(logdt[0]);
    const float A = -expf(logA[n]);
    const float Abar = expf(A * dt);
    float frac;
    if (fabsf(A) < 1e-6f) frac = dt;
    else                  frac = (Abar - 1.f) / A;
    const float Bbar = frac * Bp[n];
    const float Cc = Cp[n];

    const int base = b * L_SEQ * N_DIM;
    const int hstart = (t0 >= HALO) ? (t0 - HALO) : 0;

    float h = 0.f;
#pragma unroll 4
    for (int t = hstart; t < t0; ++t)
        h = h * Abar + u[base + t * N_DIM + n] * Bbar;
#pragma unroll 4
    for (int t = t0; t < t0 + CH; ++t) {
        h = h * Abar + u[base + t * N_DIM + n] * Bbar;
        y[base + t * N_DIM + n] = h * Cc;
    }
}

extern "C" void kernel_launch(void* const* d_in, const int* in_sizes, int n_in,
                              void* d_out, int out_size) {
    const float* x     = (const float*)d_in[0];  // (B, L, D)
    const float* W_in  = (const float*)d_in[1];  // (N, D)
    const float* W_out = (const float*)d_in[2];  // (D, N)
    const float* logA  = (const float*)d_in[3];  // (N,)
    const float* Bp    = (const float*)d_in[4];  // (N,)
    const float* Cp    = (const float*)d_in[5];  // (N,)
    const float* logdt = (const float*)d_in[6];  // scalar
    float* out = (float*)d_out;                  // (B, L, D)

    float* u_ptr = nullptr;
    float* y_ptr = nullptr;
    cudaGetSymbolAddress((void**)&u_ptr, g_u);
    cudaGetSymbolAddress((void**)&y_ptr, g_y);

    // GEMM1: u[M x N] = x[M x D] * W_in[N x D]^T
    {
        dim3 grid(M_TOT / 64, N_DIM / 64);
        gemm_abt<64, 64, 32, 4><<<grid, 256>>>(x, W_in, u_ptr, D_DIM, N_DIM);
    }
    // Scan: y = SSM(u)
    {
        dim3 grid(L_SEQ / CH, B_SZ);
        ssm_scan<<<grid, N_DIM>>>(u_ptr, y_ptr, logA, Bp, Cp, logdt);
    }
    // GEMM2: out[M x D] = y[M x N] * W_out[D x N]^T
    {
        dim3 grid(M_TOT / 128, D_DIM / 64);
        gemm_abt<128, 64, 32, 8><<<grid, 256>>>(y_ptr, W_out, out, N_DIM, D_DIM);
    }
}